// round 17
// baseline (speedup 1.0000x reference)
#include <cuda_runtime.h>

// SOM batch_train, 8192 sequential steps. Persistent 64-CTA kernel:
// 16 neuron warps + 1 comm warp per CTA (544 thr).
// R17 delta vs R16 (7412us): ABV published ~400cyc EARLIER via algebraic
// pre-reduction. A,B,V are quadratics in cp=c(t-1) whose six coefficient dot
// products (Sp,Spv,Spu,Su,Suv,Sv over p=x_{t+1}-w_old, u_o, v_o) are
// cp-independent -> computed+warp-reduced in the PREVIOUS shadow; neuron top
// = 9 scalar FMA -> STS ABV. Comm hoists flag-wait+ABV-LDS BEFORE the poll
// (safe now: ready at ~store+130 vs detect at ~store+520), shrinking the
// post-detect tail to redux->LUT->d2->redux->store and killing the race
// jitter. Inter-CTA protocol byte-identical to R16.
//
//   d2_{t+1} = A - 2*c_t*B + c_t^2*V
// sm_c/sm_ABV parity-buffered; all handoffs flag-based (no loop barriers).

#define DIM      384
#define KREG     12           // DIM / 32 dims per lane
#define NCTA     64
#define NPC      16           // neurons per CTA
#define NTHREADS 544          // 16 neuron warps + 1 comm warp
#define RING     4

// packed (d2bits:32 | tag:22 | neuron:10); zero at load, re-zeroed each launch
__device__ unsigned long long g_slots[RING][NCTA];

static __device__ __forceinline__ unsigned long long ld_rlx(const unsigned long long* p) {
    unsigned long long v;
    asm volatile("ld.relaxed.gpu.global.b64 %0, [%1];" : "=l"(v) : "l"(p) : "memory");
    return v;
}
static __device__ __forceinline__ void st_rlx(unsigned long long* p, unsigned long long v) {
    asm volatile("st.relaxed.gpu.global.b64 [%0], %1;" :: "l"(p), "l"(v) : "memory");
}

__global__ void __launch_bounds__(NTHREADS, 1)
som_kernel(const float* __restrict__ X, const float* __restrict__ W0,
           const int* __restrict__ ep, float* __restrict__ out, int n_samples)
{
    const int cta  = blockIdx.x;
    const int tid  = threadIdx.x;
    const int warp = tid >> 5;
    const int lane = tid & 31;

    int epochs = *ep;
    if (epochs < 1 || epochs > 8) epochs = 1;
    const int TS = epochs * n_samples;           // <= 65536, tags fit 22 bits

    __shared__ float c_table[63 * 63];           // 0.1*exp(-0.5*sqrt(dx^2+dy^2))
    __shared__ float4 sm_ABV[2][NPC];            // (A, -2B, V), parity-buffered
    __shared__ float sm_c[2][NPC];               // per-neuron c, parity-buffered
    __shared__ volatile int sm_flag[NPC];        // ABV-ready tag per neuron warp
    __shared__ volatile int sm_cflag;            // c-ready tag from comm warp
    __shared__ unsigned long long sm_pack[NPC];  // prologue only

    for (int i = tid; i < 63 * 63; i += NTHREADS) {
        float dx = (float)(i / 63 - 31);
        float dy = (float)(i % 63 - 31);
        c_table[i] = 0.1f * expf(-0.5f * sqrtf(dx * dx + dy * dy));
    }
    if (tid < NPC) { sm_c[1][tid] = 0.f; sm_flag[tid] = 0; }
    if (tid == 0) sm_cflag = 0;

    // ---- neuron-warp state ----
    const int n = cta * NPC + warp;              // valid for warp < 16
    float w[KREG], v[KREG], u[KREG], xn[KREG];
    float sp, spv, spu, su, suv, sv;             // six pre-reduced coefficients
    int pf = (n_samples > 2) ? 2 : (2 % n_samples);

    if (warp < NPC) {
        float a0 = 0.f, a1 = 0.f;
#pragma unroll
        for (int k = 0; k < KREG; k++) {
            float wk = W0[n * DIM + lane + 32 * k];
            w[k] = wk;
            v[k] = 0.f;
            float t0 = X[lane + 32 * k] - wk;    // u = x0 - w0
            u[k] = t0;
            if (k & 1) a1 = fmaf(t0, t0, a1); else a0 = fmaf(t0, t0, a0);
        }
        float d2 = a0 + a1;
#pragma unroll
        for (int off = 16; off; off >>= 1)
            d2 += __shfl_xor_sync(0xFFFFFFFFu, d2, off);
#pragma unroll
        for (int k = 0; k < KREG; k++) xn[k] = X[DIM + lane + 32 * k];   // x1

        // six sums for transition 0 (v = 0 -> Spv=Suv=Sv=0 naturally)
        sp = spv = spu = su = suv = sv = 0.f;
#pragma unroll
        for (int k = 0; k < KREG; k++) {
            float pk = xn[k] - w[k];
            sp  = fmaf(pk, pk, sp);   spv = fmaf(pk, v[k], spv);
            spu = fmaf(pk, u[k], spu); su = fmaf(u[k], u[k], su);
            suv = fmaf(u[k], v[k], suv); sv = fmaf(v[k], v[k], sv);
        }
#pragma unroll
        for (int off = 16; off; off >>= 1) {
            sp  += __shfl_xor_sync(0xFFFFFFFFu, sp,  off);
            spv += __shfl_xor_sync(0xFFFFFFFFu, spv, off);
            spu += __shfl_xor_sync(0xFFFFFFFFu, spu, off);
            su  += __shfl_xor_sync(0xFFFFFFFFu, su,  off);
            suv += __shfl_xor_sync(0xFFFFFFFFu, suv, off);
            sv  += __shfl_xor_sync(0xFFFFFFFFu, sv,  off);
        }

        if (lane == 0)
            sm_pack[warp] = ((unsigned long long)__float_as_uint(d2) << 32)
                          | ((1u << 10) | (unsigned)n);
    }

    __syncthreads();     // prologue only: packs + sm_c[1] + flags + LUT visible

    if (warp == NPC) {                           // store candidate(0), tag 1
        unsigned long long p = (lane < NPC) ? sm_pack[lane] : 0xFFFFFFFFFFFFFFFFull;
        unsigned phi = (unsigned)(p >> 32), plo = (unsigned)p;
        unsigned mhi = __reduce_min_sync(0xFFFFFFFFu, phi);
        unsigned cnd = (phi == mhi) ? plo : 0xFFFFFFFFu;
        unsigned mlo = __reduce_min_sync(0xFFFFFFFFu, cnd);
        if (lane == 0)
            st_rlx(&g_slots[0][cta], ((unsigned long long)mhi << 32) | mlo);
    }

    const int nl = cta * NPC + (lane & 15);      // comm-lane neuron id (in range)
    const int lut_base = (nl >> 5) * 63 + (nl & 31) + (31 * 63 + 31);

    if (warp == NPC) {
        // =================== comm warp: whole loop ===================
        for (int t = 0; t < TS; ++t) {
            const int par = t & 1;

            // ---- (a) ABV(t) frontload: ready ~store+130, detect ~store+520 ----
            {
                bool ok;
                do {
                    ok = (lane >= NPC) || (sm_flag[lane] == t + 1);
                } while (!__all_sync(0xFFFFFFFFu, ok));
            }
            __threadfence_block();
            const float4 q = sm_ABV[par][lane & 15];      // (A, -2B, V)

            // ---- (b) software-pipelined poll for bmu(t) ----
            const unsigned tag = (unsigned)(t + 1) & 0x3FFFFFu;
            const int ring = t & (RING - 1);
            unsigned long long* p0 = &g_slots[ring][lane];
            unsigned long long* p1 = &g_slots[ring][lane + 32];
            unsigned long long v0, v1;
            {
                unsigned long long a0 = ld_rlx(p0), a1 = ld_rlx(p1);
                for (;;) {
                    unsigned long long b0 = ld_rlx(p0), b1 = ld_rlx(p1);
                    bool ok = ((((unsigned)a0) >> 10) == tag) &&
                              ((((unsigned)a1) >> 10) == tag);
                    if (__all_sync(0xFFFFFFFFu, ok)) { v0 = a0; v1 = a1; break; }
                    a0 = b0; a1 = b1;
                }
            }
            unsigned long long vm = (v0 < v1) ? v0 : v1;
            unsigned qhi = (unsigned)(vm >> 32), qlo = (unsigned)vm;
            unsigned gh = __reduce_min_sync(0xFFFFFFFFu, qhi);
            unsigned gc = (qhi == gh) ? qlo : 0xFFFFFFFFu;
            unsigned gl = __reduce_min_sync(0xFFFFFFFFu, gc);
            const int bmu = (int)(gl & 0x3FFu);

            // ---- (c) short critical tail: LUT, d2, CTA argmin, store ----
            const float ci = c_table[lut_base - (bmu >> 5) * 63 - (bmu & 31)];
            if (t + 1 < TS) {
                float d2 = fmaxf(fmaf(ci, fmaf(ci, q.z, q.y), q.x), 0.f);
                unsigned tag2 = (unsigned)(t + 2) & 0x3FFFFFu;
                unsigned long long pk = (lane < NPC)
                    ? (((unsigned long long)__float_as_uint(d2) << 32)
                       | ((tag2 << 10) | (unsigned)nl))
                    : 0xFFFFFFFFFFFFFFFFull;
                unsigned phi2 = (unsigned)(pk >> 32), plo2 = (unsigned)pk;
                unsigned mhi2 = __reduce_min_sync(0xFFFFFFFFu, phi2);
                unsigned cnd2 = (phi2 == mhi2) ? plo2 : 0xFFFFFFFFu;
                unsigned mlo2 = __reduce_min_sync(0xFFFFFFFFu, cnd2);
                if (lane == 0)
                    st_rlx(&g_slots[(t + 1) & (RING - 1)][cta],
                           ((unsigned long long)mhi2 << 32) | mlo2);
            }
            // ---- (d) off-chain: publish c(t), then straight to next iter ----
            if (lane < NPC) sm_c[par][lane] = ci;
            __threadfence_block();
            if (lane == 0) sm_cflag = t + 1;
        }

        // ---- termination handshake + scratch cleanup (deterministic replays) ----
        const unsigned ftag = (unsigned)(TS + 1) & 0x3FFFFFu;
        const int fring = TS & (RING - 1);
        if (lane == 0)
            st_rlx(&g_slots[fring][cta], (unsigned long long)(ftag << 10));

        if (cta == 0) {
            for (;;) {
                unsigned long long v0 = ld_rlx(&g_slots[fring][lane]);
                unsigned long long v1 = ld_rlx(&g_slots[fring][lane + 32]);
                bool ok = ((((unsigned)v0) >> 10) == ftag) &&
                          ((((unsigned)v1) >> 10) == ftag);
                if (__all_sync(0xFFFFFFFFu, ok)) break;
            }
#pragma unroll
            for (int r = 0; r < RING; r++) {
                st_rlx(&g_slots[r][lane], 0ull);
                st_rlx(&g_slots[r][lane + 32], 0ull);
            }
            __threadfence();
        }
    } else {
        // =================== neuron warps: whole loop ===================
        for (int t = 0; t < TS; ++t) {
            const int par = t & 1;

            // polite spin (R15): c(t-1) published at cflag==t
            if (sm_cflag < t) {
                do { __nanosleep(40); } while (sm_cflag < t);
            }
            __threadfence_block();
            const float cp = sm_c[par ^ 1][warp];    // c(t-1)

            // ---- FAST PATH: ABV(t) from six pre-reduced sums, 9 FMA ----
            {
                float A = fmaf(cp, fmaf(cp, sv, -2.f * spv), sp);
                float B = fmaf(cp, fmaf(cp, sv, -(spv + suv)), spu);
                float V = fmaf(cp, fmaf(cp, sv, -2.f * suv), su);
                if (lane == 0) {
                    sm_ABV[par][warp] = make_float4(A, -2.f * B, V, 0.f);
                    __threadfence_block();
                    sm_flag[warp] = t + 1;           // ABV(t) ready EARLY
                }
            }

            // ---- shadow: updates, prefetch, six sums for t+1 ----
#pragma unroll
            for (int k = 0; k < KREG; k++) {
                float vo = v[k];
                w[k] = fmaf(cp, vo, w[k]);
                v[k] = fmaf(-cp, vo, u[k]);
                u[k] = xn[k] - w[k];
            }
            const float* xp = X + (size_t)pf * DIM + lane;   // prefetch x(t+2)
#pragma unroll
            for (int k = 0; k < KREG; k++) xn[k] = xp[32 * k];
            pf++; if (pf == n_samples) pf = 0;

            sp = spv = spu = su = suv = sv = 0.f;
#pragma unroll
            for (int k = 0; k < KREG; k++) {
                float pk = xn[k] - w[k];             // p = x(t+2) - w(t)
                sp  = fmaf(pk, pk, sp);   spv = fmaf(pk, v[k], spv);
                spu = fmaf(pk, u[k], spu); su = fmaf(u[k], u[k], su);
                suv = fmaf(u[k], v[k], suv); sv = fmaf(v[k], v[k], sv);
            }
#pragma unroll
            for (int off = 16; off; off >>= 1) {
                sp  += __shfl_xor_sync(0xFFFFFFFFu, sp,  off);
                spv += __shfl_xor_sync(0xFFFFFFFFu, spv, off);
                spu += __shfl_xor_sync(0xFFFFFFFFu, spu, off);
                su  += __shfl_xor_sync(0xFFFFFFFFu, su,  off);
                suv += __shfl_xor_sync(0xFFFFFFFFu, suv, off);
                sv  += __shfl_xor_sync(0xFFFFFFFFu, sv,  off);
            }
        }

        // epilogue: apply final update c(TS-1), write weights
        if (sm_cflag < TS) {
            do { __nanosleep(40); } while (sm_cflag < TS);
        }
        __threadfence_block();
        const float cp = sm_c[(TS - 1) & 1][warp];
#pragma unroll
        for (int k = 0; k < KREG; k++)
            out[n * DIM + lane + 32 * k] = fmaf(cp, v[k], w[k]);
    }
}

extern "C" void kernel_launch(void* const* d_in, const int* in_sizes, int n_in,
                              void* d_out, int out_size)
{
    const float* X  = (const float*)d_in[0];   // [8192, 384]
    const float* W0 = (const float*)d_in[1];   // [32, 32, 384]
    const int*   ep = (const int*)d_in[3];     // num_epochs
    float* out = (float*)d_out;                // [32, 32, 384]

    int n_samples = in_sizes[0] / DIM;
    som_kernel<<<NCTA, NTHREADS>>>(X, W0, ep, out, n_samples);
}